// round 14
// baseline (speedup 1.0000x reference)
#include <cuda_runtime.h>
#include <cuda_bf16.h>
#include <cstdint>

#define T_TOKENS 16384
#define H_DIM    4096
#define N_EXP    64
#define CAP      320

__device__ __align__(16) int g_idx[2 * T_TOKENS];
__device__ __align__(16) int g_cnt[256 * N_EXP];    // [segment][expert]
__device__ __align__(16) int g_base[256 * N_EXP];   // exclusive prefix per expert
__device__ __align__(16) __nv_bfloat16 g_whi[N_EXP * H_DIM];
__device__ __align__(16) __nv_bfloat16 g_wlo[N_EXP * H_DIM];
__device__ __align__(16) float g_part[2 * T_TOKENS * N_EXP];   // split-K partials (8 MB)

// ---------------------------------------------------------------------------
// helpers
// ---------------------------------------------------------------------------
__device__ __forceinline__ uint32_t smem_to_u32(const void* p) {
    uint32_t a;
    asm("{ .reg .u64 t; cvta.to.shared.u64 t, %1; cvt.u32.u64 %0, t; }" : "=r"(a) : "l"(p));
    return a;
}

#define LDSM_X4(r0, r1, r2, r3, addr)                                          \
    asm volatile("ldmatrix.sync.aligned.m8n8.x4.shared.b16 {%0,%1,%2,%3}, [%4];" \
                 : "=r"(r0), "=r"(r1), "=r"(r2), "=r"(r3) : "r"(addr))

#define MMA16816(d, a0, a1, a2, a3, b0, b1)                                        \
    asm volatile(                                                                  \
        "mma.sync.aligned.m16n8k16.row.col.f32.bf16.bf16.f32 "                     \
        "{%0,%1,%2,%3}, {%4,%5,%6,%7}, {%8,%9}, {%0,%1,%2,%3};"                    \
        : "+f"((d)[0]), "+f"((d)[1]), "+f"((d)[2]), "+f"((d)[3])                   \
        : "r"(a0), "r"(a1), "r"(a2), "r"(a3), "r"(b0), "r"(b1))

__device__ __forceinline__ void cvt_split4(float4 f, uint32_t& h0, uint32_t& h1,
                                           uint32_t& l0, uint32_t& l1) {
    __nv_bfloat162 a = __floats2bfloat162_rn(f.x, f.y);
    __nv_bfloat162 b = __floats2bfloat162_rn(f.z, f.w);
    float r0 = f.x - __bfloat162float(a.x);
    float r1 = f.y - __bfloat162float(a.y);
    float r2 = f.z - __bfloat162float(b.x);
    float r3 = f.w - __bfloat162float(b.y);
    __nv_bfloat162 c = __floats2bfloat162_rn(r0, r1);
    __nv_bfloat162 d = __floats2bfloat162_rn(r2, r3);
    h0 = *(uint32_t*)&a; h1 = *(uint32_t*)&b;
    l0 = *(uint32_t*)&c; l1 = *(uint32_t*)&d;
}

// (value, index) "strictly better" with jax top_k tie-break (lower index wins)
__device__ __forceinline__ bool vgt(float v1, int i1, float v2, int i2) {
    return (v1 > v2) || (v1 == v2 && i1 < i2);
}

// ---------------------------------------------------------------------------
// smem: per buffer (BK=64): Ahi[128x64 bf16, stride 144B]=18432, Alo=18432,
// Bhi[64x64]=9216, Blo=9216 -> 55296; x2 = 110592 bytes (2 CTAs/SM = 221 KB).
// ---------------------------------------------------------------------------
#define SA_STRIDE 144
#define BUF_BYTES 55296
#define OFF_AHI(b) ((b) * BUF_BYTES + 0)
#define OFF_ALO(b) ((b) * BUF_BYTES + 18432)
#define OFF_BHI(b) ((b) * BUF_BYTES + 36864)
#define OFF_BLO(b) ((b) * BUF_BYTES + 46080)
#define SMEM_BYTES (2 * BUF_BYTES)

#define K_HALF    2048
#define NCHUNK_H  32      // 32 chunks of 64 per K half

// ---------------------------------------------------------------------------
// W pre-convert: fp32 -> bf16 hi + lo
// ---------------------------------------------------------------------------
__global__ __launch_bounds__(256)
void wconv_kernel(const float* __restrict__ W) {
    const int i = (blockIdx.x * 256 + threadIdx.x) * 4;
    float4 f = *(const float4*)(W + i);
    uint32_t h0, h1, l0, l1;
    cvt_split4(f, h0, h1, l0, l1);
    *(uint2*)(g_whi + i) = make_uint2(h0, h1);
    *(uint2*)(g_wlo + i) = make_uint2(l0, l1);
}

// ---------------------------------------------------------------------------
// Split-K GEMM partial: grid (128 m-tiles, 2 k-halves), 256 threads, 8 warps
// 4M x 2N (warp tile 32x32 -> 171 B LDSM per MMA). 2 CTAs/SM co-resident.
// ---------------------------------------------------------------------------
__global__ __launch_bounds__(256, 2)
void gemm_partial_kernel(const float* __restrict__ A) {
    extern __shared__ char smem[];
    const uint32_t sb = smem_to_u32(smem);
    const int tid  = threadIdx.x;
    const int wid  = tid >> 5;
    const int lane = tid & 31;
    const int wm   = wid & 3;     // rows [wm*32, +32)
    const int wn   = wid >> 2;    // cols [wn*32, +32)
    const int bm   = blockIdx.x;
    const int ks   = blockIdx.y;  // K half
    const int block_m = bm * 128;

    // global load coords
    const int a_row  = tid >> 1;       // 0..127
    const int a_half = tid & 1;        // 32-float half of 64-wide chunk
    const int b_row  = tid >> 2;       // 0..63
    const int b_o    = (tid & 3) * 16; // 16 bf16

    const float* Abase = A + (size_t)(block_m + a_row) * H_DIM + ks * K_HALF + a_half * 32;
    const __nv_bfloat16* Whi = g_whi + (size_t)b_row * H_DIM + ks * K_HALF + b_o;
    const __nv_bfloat16* Wlo = g_wlo + (size_t)b_row * H_DIM + ks * K_HALF + b_o;

    const uint32_t a_lds = (uint32_t)((wm * 32 + (lane & 15)) * SA_STRIDE + (lane >> 4) * 16);
    const uint32_t b_lds = (uint32_t)((wn * 32 + (lane & 7) + ((lane >> 4) & 1) * 8) * SA_STRIDE +
                                      ((lane >> 3) & 1) * 16);

    float acc[2][4][4];
    #pragma unroll
    for (int i = 0; i < 2; i++)
        #pragma unroll
        for (int j = 0; j < 4; j++)
            #pragma unroll
            for (int q = 0; q < 4; q++) acc[i][j][q] = 0.0f;

    float4 fA[8];
    uint4 bh0, bh1, bl0, bl1;

    // ---- prologue: chunk 0 -> buffer 0 ----
    #pragma unroll
    for (int i = 0; i < 8; i++) fA[i] = ((const float4*)Abase)[i];
    bh0 = ((const uint4*)Whi)[0];
    bh1 = ((const uint4*)Whi)[1];
    bl0 = ((const uint4*)Wlo)[0];
    bl1 = ((const uint4*)Wlo)[1];
    {
        char* ah = smem + OFF_AHI(0) + a_row * SA_STRIDE + a_half * 64;
        char* al = smem + OFF_ALO(0) + a_row * SA_STRIDE + a_half * 64;
        #pragma unroll
        for (int i = 0; i < 4; i++) {
            uint32_t h[4], l[4];
            cvt_split4(fA[i * 2 + 0], h[0], h[1], l[0], l[1]);
            cvt_split4(fA[i * 2 + 1], h[2], h[3], l[2], l[3]);
            *(uint4*)(ah + i * 16) = *(uint4*)h;
            *(uint4*)(al + i * 16) = *(uint4*)l;
        }
        char* bhp = smem + OFF_BHI(0) + b_row * SA_STRIDE + b_o * 2;
        char* blp = smem + OFF_BLO(0) + b_row * SA_STRIDE + b_o * 2;
        *(uint4*)(bhp)      = bh0;
        *(uint4*)(bhp + 16) = bh1;
        *(uint4*)(blp)      = bl0;
        *(uint4*)(blp + 16) = bl1;
    }
    __syncthreads();

    for (int kc = 0; kc < NCHUNK_H; kc++) {
        const int b = kc & 1;
        const bool has_next = (kc + 1 < NCHUNK_H);

        if (has_next) {
            const float* ga = Abase + (kc + 1) * 64;
            #pragma unroll
            for (int i = 0; i < 8; i++) fA[i] = ((const float4*)ga)[i];
            const __nv_bfloat16* wh = Whi + (kc + 1) * 64;
            const __nv_bfloat16* wl = Wlo + (kc + 1) * 64;
            bh0 = ((const uint4*)wh)[0];
            bh1 = ((const uint4*)wh)[1];
            bl0 = ((const uint4*)wl)[0];
            bl1 = ((const uint4*)wl)[1];
        }

        const uint32_t ahi_b = sb + OFF_AHI(b) + a_lds;
        const uint32_t alo_b = sb + OFF_ALO(b) + a_lds;
        const uint32_t bhi_b = sb + OFF_BHI(b) + b_lds;
        const uint32_t blo_b = sb + OFF_BLO(b) + b_lds;

        #pragma unroll
        for (int ksu = 0; ksu < 4; ksu++) {
            const uint32_t kb = ksu * 32;
            uint32_t ah[2][4], al[2][4], bh[2][4], bl[2][4];
            #pragma unroll
            for (int mi = 0; mi < 2; mi++) {
                LDSM_X4(ah[mi][0], ah[mi][1], ah[mi][2], ah[mi][3],
                        ahi_b + mi * 16 * SA_STRIDE + kb);
                LDSM_X4(al[mi][0], al[mi][1], al[mi][2], al[mi][3],
                        alo_b + mi * 16 * SA_STRIDE + kb);
            }
            #pragma unroll
            for (int nt = 0; nt < 2; nt++) {
                LDSM_X4(bh[nt][0], bh[nt][1], bh[nt][2], bh[nt][3],
                        bhi_b + nt * 16 * SA_STRIDE + kb);
                LDSM_X4(bl[nt][0], bl[nt][1], bl[nt][2], bl[nt][3],
                        blo_b + nt * 16 * SA_STRIDE + kb);
            }
            #pragma unroll
            for (int mi = 0; mi < 2; mi++) {
                #pragma unroll
                for (int nt = 0; nt < 2; nt++) {
                    MMA16816(acc[mi][nt * 2 + 0], ah[mi][0], ah[mi][1], ah[mi][2], ah[mi][3],
                             bh[nt][0], bh[nt][1]);
                    MMA16816(acc[mi][nt * 2 + 1], ah[mi][0], ah[mi][1], ah[mi][2], ah[mi][3],
                             bh[nt][2], bh[nt][3]);
                    MMA16816(acc[mi][nt * 2 + 0], ah[mi][0], ah[mi][1], ah[mi][2], ah[mi][3],
                             bl[nt][0], bl[nt][1]);
                    MMA16816(acc[mi][nt * 2 + 1], ah[mi][0], ah[mi][1], ah[mi][2], ah[mi][3],
                             bl[nt][2], bl[nt][3]);
                    MMA16816(acc[mi][nt * 2 + 0], al[mi][0], al[mi][1], al[mi][2], al[mi][3],
                             bh[nt][0], bh[nt][1]);
                    MMA16816(acc[mi][nt * 2 + 1], al[mi][0], al[mi][1], al[mi][2], al[mi][3],
                             bh[nt][2], bh[nt][3]);
                }
            }
        }

        if (has_next) {
            const int nb = b ^ 1;
            __syncthreads();
            char* ah = smem + OFF_AHI(nb) + a_row * SA_STRIDE + a_half * 64;
            char* al = smem + OFF_ALO(nb) + a_row * SA_STRIDE + a_half * 64;
            #pragma unroll
            for (int i = 0; i < 4; i++) {
                uint32_t h[4], l[4];
                cvt_split4(fA[i * 2 + 0], h[0], h[1], l[0], l[1]);
                cvt_split4(fA[i * 2 + 1], h[2], h[3], l[2], l[3]);
                *(uint4*)(ah + i * 16) = *(uint4*)h;
                *(uint4*)(al + i * 16) = *(uint4*)l;
            }
            char* bhp = smem + OFF_BHI(nb) + b_row * SA_STRIDE + b_o * 2;
            char* blp = smem + OFF_BLO(nb) + b_row * SA_STRIDE + b_o * 2;
            *(uint4*)(bhp)      = bh0;
            *(uint4*)(bhp + 16) = bh1;
            *(uint4*)(blp)      = bl0;
            *(uint4*)(blp + 16) = bl1;
            __syncthreads();
        }
    }

    // ---- epilogue: write partial C directly to g_part[ks] ----
    float* P = g_part + ((size_t)ks << 20);   // 16384*64 = 1<<20
    #pragma unroll
    for (int mi = 0; mi < 2; mi++) {
        #pragma unroll
        for (int ni = 0; ni < 4; ni++) {
            int r0 = wm * 32 + mi * 16 + (lane >> 2);
            int c  = wn * 32 + ni * 8 + (lane & 3) * 2;
            *(float2*)(P + (size_t)(block_m + r0) * N_EXP + c) =
                make_float2(acc[mi][ni][0], acc[mi][ni][1]);
            *(float2*)(P + (size_t)(block_m + r0 + 8) * N_EXP + c) =
                make_float2(acc[mi][ni][2], acc[mi][ni][3]);
        }
    }
}

// ---------------------------------------------------------------------------
// Reduce + top-2 + hist: 128 blocks x 512 threads. Thread = (row r, quarter q).
// Sums the two K-half partials (order-invariant 2-addend fp32 add), writes
// logits, shfl-merges top-2 over 4 threads, histograms into g_cnt.
// ---------------------------------------------------------------------------
__global__ __launch_bounds__(512)
void topk_kernel(float* __restrict__ logits, float* __restrict__ wflat) {
    __shared__ int cnts[128];
    const int tid = threadIdx.x;
    const int bm  = blockIdx.x;
    const int block_m = bm * 128;

    if (tid < 128) cnts[tid] = 0;
    __syncthreads();

    const int r  = tid >> 2;
    const int q  = tid & 3;
    const int cb = q * 16;

    const float* p0 = g_part + (size_t)(block_m + r) * N_EXP + cb;
    const float* p1 = p0 + (1 << 20);
    float* lrow = logits + (size_t)(block_m + r) * N_EXP + cb;

    float m1 = -3.4e38f, m2 = -3.4e38f;
    int i1 = 0, i2 = 0;
    #pragma unroll
    for (int i = 0; i < 4; i++) {
        float4 u = *(const float4*)(p0 + i * 4);
        float4 v = *(const float4*)(p1 + i * 4);
        float4 s = make_float4(u.x + v.x, u.y + v.y, u.z + v.z, u.w + v.w);
        *(float4*)(lrow + i * 4) = s;
        float vals[4] = {s.x, s.y, s.z, s.w};
        #pragma unroll
        for (int j = 0; j < 4; j++) {
            float val = vals[j];
            int e = cb + i * 4 + j;
            if (val > m1)      { m2 = m1; i2 = i1; m1 = val; i1 = e; }
            else if (val > m2) { m2 = val; i2 = e; }
        }
    }

    // butterfly merge across the 4 quarter-threads (lane bits 0,1)
    #pragma unroll
    for (int msk = 1; msk <= 2; msk <<= 1) {
        float om1 = __shfl_xor_sync(0xffffffffu, m1, msk);
        int   oi1 = __shfl_xor_sync(0xffffffffu, i1, msk);
        float om2 = __shfl_xor_sync(0xffffffffu, m2, msk);
        int   oi2 = __shfl_xor_sync(0xffffffffu, i2, msk);
        if (vgt(om1, oi1, m1, i1)) {
            if (vgt(m1, i1, om2, oi2)) { m2 = m1; i2 = i1; }
            else                       { m2 = om2; i2 = oi2; }
            m1 = om1; i1 = oi1;
        } else {
            if (vgt(om1, oi1, m2, i2)) { m2 = om1; i2 = oi1; }
        }
    }

    if (q == 0) {
        const int t = block_m + r;
        float w1 = 1.0f / (1.0f + __expf(m2 - m1));
        wflat[t * 2 + 0] = w1;
        wflat[t * 2 + 1] = 1.0f - w1;
        g_idx[t]            = i1;
        g_idx[T_TOKENS + t] = i2;
        atomicAdd(&cnts[i1], 1);
        atomicAdd(&cnts[64 + i2], 1);
    }
    __syncthreads();
    if (tid < 64) {    // block owns segments bm (slot0) and 128+bm (slot1)
        g_cnt[bm * 64 + tid]         = cnts[tid];
        g_cnt[(128 + bm) * 64 + tid] = cnts[64 + tid];
    }
}

// ---------------------------------------------------------------------------
// Scan: one block per expert; 256-wide exclusive prefix over segment counts.
// Also zeros the unwritten tail [total, CAP) of this expert's output rows.
// ---------------------------------------------------------------------------
__global__ __launch_bounds__(256)
void scan_kernel(float* __restrict__ out_idx, float* __restrict__ out_w) {
    const int e = blockIdx.x;
    const int tid = threadIdx.x;
    const int lane = tid & 31, w = tid >> 5;

    int c = g_cnt[tid * N_EXP + e];
    int incl = c;
    #pragma unroll
    for (int off = 1; off < 32; off <<= 1) {
        int n = __shfl_up_sync(0xffffffffu, incl, off);
        if (lane >= off) incl += n;
    }
    __shared__ int wtot[8];
    if (lane == 31) wtot[w] = incl;
    __syncthreads();
    int woff = 0, total = 0;
    #pragma unroll
    for (int ww = 0; ww < 8; ww++) {
        int s = wtot[ww];
        if (ww < w) woff += s;
        total += s;
    }
    g_base[tid * N_EXP + e] = woff + incl - c;

    for (int i = total + tid; i < CAP; i += 256) {
        out_idx[e * CAP + i] = 0.0f;
        out_w[e * CAP + i]   = 0.0f;
    }
}

// ---------------------------------------------------------------------------
// Assign: grid (64 experts, 32), 8 warps/block; each warp handles one
// 128-entry segment: one int4 per lane, warp rank scan, scatter.
// ---------------------------------------------------------------------------
__global__ __launch_bounds__(256)
void assign_kernel(const float* __restrict__ wflat,
                   float* __restrict__ out_idx,
                   float* __restrict__ out_w) {
    const int e    = blockIdx.x;
    const int tid  = threadIdx.x;
    const int lane = tid & 31;
    const int s    = blockIdx.y * 8 + (tid >> 5);   // segment 0..255

    const int base = g_base[s * N_EXP + e];
    int4 v = ((const int4*)g_idx)[s * 32 + lane];

    int m0 = (v.x == e), m1 = (v.y == e), m2 = (v.z == e), m3 = (v.w == e);
    int cnt = m0 + m1 + m2 + m3;
    int inc = cnt;
    #pragma unroll
    for (int off = 1; off < 32; off <<= 1) {
        int n = __shfl_up_sync(0xffffffffu, inc, off);
        if (lane >= off) inc += n;
    }
    int pos = base + inc - cnt;

    if (cnt) {
        const int a0 = s * 128 + lane * 4;
        int comp[4] = {v.x, v.y, v.z, v.w};
        #pragma unroll
        for (int q = 0; q < 4; q++) {
            if (comp[q] == e) {
                if (pos < CAP) {
                    int a = a0 + q;
                    int token = a & (T_TOKENS - 1);
                    int slot  = a >> 14;
                    out_idx[e * CAP + pos] = (float)token;
                    out_w[e * CAP + pos]   = wflat[token * 2 + slot];
                }
                pos++;
            }
        }
    }
}

// ---------------------------------------------------------------------------
// Output layout (float32): [idx E*CAP | w E*CAP | wflat T*2 | logits T*E]
// ---------------------------------------------------------------------------
extern "C" void kernel_launch(void* const* d_in, const int* in_sizes, int n_in,
                              void* d_out, int out_size) {
    const float* hs;
    const float* wr;
    if (in_sizes[0] == N_EXP * H_DIM) {
        wr = (const float*)d_in[0];
        hs = (const float*)d_in[1];
    } else {
        hs = (const float*)d_in[0];
        wr = (const float*)d_in[1];
    }

    float* out     = (float*)d_out;
    float* out_idx = out;
    float* out_w   = out + N_EXP * CAP;
    float* wflat   = out + 2 * N_EXP * CAP;
    float* logits  = out + 2 * N_EXP * CAP + 2 * T_TOKENS;

    wconv_kernel<<<256, 256>>>(wr);
    cudaFuncSetAttribute(gemm_partial_kernel, cudaFuncAttributeMaxDynamicSharedMemorySize,
                         SMEM_BYTES);
    gemm_partial_kernel<<<dim3(T_TOKENS / 128, 2), 256, SMEM_BYTES>>>(hs);
    topk_kernel<<<T_TOKENS / 128, 512>>>(logits, wflat);
    scan_kernel<<<N_EXP, 256>>>(out_idx, out_w);
    assign_kernel<<<dim3(N_EXP, 32), 256>>>(wflat, out_idx, out_w);
}

// round 15
// speedup vs baseline: 1.3911x; 1.3911x over previous
#include <cuda_runtime.h>
#include <cuda_bf16.h>
#include <cstdint>

#define T_TOKENS 16384
#define H_DIM    4096
#define N_EXP    64
#define CAP      320

__device__ __align__(16) int g_idx[2 * T_TOKENS];
__device__ __align__(16) int g_cnt[N_EXP * 256];    // [expert][segment]
__device__ __align__(16) int g_base[N_EXP * 256];   // [expert][segment] excl prefix
__device__ __align__(16) __nv_bfloat16 g_whi[N_EXP * H_DIM];
__device__ __align__(16) __nv_bfloat16 g_wlo[N_EXP * H_DIM];

// ---------------------------------------------------------------------------
// helpers
// ---------------------------------------------------------------------------
__device__ __forceinline__ uint32_t smem_to_u32(const void* p) {
    uint32_t a;
    asm("{ .reg .u64 t; cvta.to.shared.u64 t, %1; cvt.u32.u64 %0, t; }" : "=r"(a) : "l"(p));
    return a;
}

#define LDSM_X4(r0, r1, r2, r3, addr)                                          \
    asm volatile("ldmatrix.sync.aligned.m8n8.x4.shared.b16 {%0,%1,%2,%3}, [%4];" \
                 : "=r"(r0), "=r"(r1), "=r"(r2), "=r"(r3) : "r"(addr))

#define MMA16816(d, a0, a1, a2, a3, b0, b1)                                        \
    asm volatile(                                                                  \
        "mma.sync.aligned.m16n8k16.row.col.f32.bf16.bf16.f32 "                     \
        "{%0,%1,%2,%3}, {%4,%5,%6,%7}, {%8,%9}, {%0,%1,%2,%3};"                    \
        : "+f"((d)[0]), "+f"((d)[1]), "+f"((d)[2]), "+f"((d)[3])                   \
        : "r"(a0), "r"(a1), "r"(a2), "r"(a3), "r"(b0), "r"(b1))

__device__ __forceinline__ void cvt_split4(float4 f, uint32_t& h0, uint32_t& h1,
                                           uint32_t& l0, uint32_t& l1) {
    __nv_bfloat162 a = __floats2bfloat162_rn(f.x, f.y);
    __nv_bfloat162 b = __floats2bfloat162_rn(f.z, f.w);
    float r0 = f.x - __bfloat162float(a.x);
    float r1 = f.y - __bfloat162float(a.y);
    float r2 = f.z - __bfloat162float(b.x);
    float r3 = f.w - __bfloat162float(b.y);
    __nv_bfloat162 c = __floats2bfloat162_rn(r0, r1);
    __nv_bfloat162 d = __floats2bfloat162_rn(r2, r3);
    h0 = *(uint32_t*)&a; h1 = *(uint32_t*)&b;
    l0 = *(uint32_t*)&c; l1 = *(uint32_t*)&d;
}

// (value, index) "strictly better" with jax top_k tie-break (lower index wins)
__device__ __forceinline__ bool vgt(float v1, int i1, float v2, int i2) {
    return (v1 > v2) || (v1 == v2 && i1 < i2);
}

// ---------------------------------------------------------------------------
// smem: per buffer (BK=64): Ahi[128x64 bf16, stride 144B]=18432, Alo=18432,
// Bhi[64x64]=9216, Blo=9216 -> 55296; x2 = 110592 bytes.
// Epilogue: C (128x66 fp32 = 33792B) + counters (512B at 34048) reuse buf0.
// ---------------------------------------------------------------------------
#define SA_STRIDE 144
#define BUF_BYTES 55296
#define OFF_AHI(b) ((b) * BUF_BYTES + 0)
#define OFF_ALO(b) ((b) * BUF_BYTES + 18432)
#define OFF_BHI(b) ((b) * BUF_BYTES + 36864)
#define OFF_BLO(b) ((b) * BUF_BYTES + 46080)
#define SMEM_BYTES (2 * BUF_BYTES)
#define CS 66
#define CNT_OFF 34048

#define NCHUNK 64

// ---------------------------------------------------------------------------
// W pre-convert: fp32 -> bf16 hi + lo.  256 blocks x 256 thr, 4 floats/thread.
// ---------------------------------------------------------------------------
__global__ __launch_bounds__(256)
void wconv_kernel(const float* __restrict__ W) {
    const int i = (blockIdx.x * 256 + threadIdx.x) * 4;
    float4 f = *(const float4*)(W + i);
    uint32_t h0, h1, l0, l1;
    cvt_split4(f, h0, h1, l0, l1);
    *(uint2*)(g_whi + i) = make_uint2(h0, h1);
    *(uint2*)(g_wlo + i) = make_uint2(l0, l1);
}

// ---------------------------------------------------------------------------
// Fused GEMM (bf16 3-product split) + top-2 + per-segment hist epilogue.
// CTA: 128 tokens x 64 experts, K=4096. 512 threads, 16 warps: 4 M x 4 N.
// ---------------------------------------------------------------------------
__global__ __launch_bounds__(512, 1)
void gemm_topk_kernel(const float* __restrict__ A,
                      float* __restrict__ logits,
                      float* __restrict__ wflat) {
    extern __shared__ char smem[];
    const uint32_t sb = smem_to_u32(smem);
    const int tid  = threadIdx.x;
    const int wid  = tid >> 5;
    const int lane = tid & 31;
    const int wm   = wid & 3;     // rows [wm*32, +32)
    const int wn   = wid >> 2;    // cols [wn*16, +16)
    const int bm   = blockIdx.x;
    const int block_m = bm * 128;

    // global load coords
    const int a_row = tid >> 2;        // 0..127
    const int a_q   = tid & 3;         // 16-float quarter of 64-wide chunk
    const int b_row = tid >> 3;        // 0..63
    const int b_o   = (tid & 7) * 8;   // 8 bf16

    const float* Abase = A + (size_t)(block_m + a_row) * H_DIM + a_q * 16;
    const __nv_bfloat16* Whi = g_whi + (size_t)b_row * H_DIM + b_o;
    const __nv_bfloat16* Wlo = g_wlo + (size_t)b_row * H_DIM + b_o;

    const uint32_t a_lds = (uint32_t)((wm * 32 + (lane & 15)) * SA_STRIDE + (lane >> 4) * 16);
    const uint32_t b_lds = (uint32_t)((wn * 16 + (lane & 7) + ((lane >> 4) & 1) * 8) * SA_STRIDE +
                                      ((lane >> 3) & 1) * 16);

    float acc[2][2][4];
    #pragma unroll
    for (int i = 0; i < 2; i++)
        #pragma unroll
        for (int j = 0; j < 2; j++)
            #pragma unroll
            for (int q = 0; q < 4; q++) acc[i][j][q] = 0.0f;

    float4 fA[4];
    uint4 bhv, blv;

    // ---- prologue: chunk 0 -> buffer 0 ----
    #pragma unroll
    for (int i = 0; i < 4; i++) fA[i] = ((const float4*)Abase)[i];
    bhv = *(const uint4*)Whi;
    blv = *(const uint4*)Wlo;
    {
        char* ah = smem + OFF_AHI(0) + a_row * SA_STRIDE + a_q * 32;
        char* al = smem + OFF_ALO(0) + a_row * SA_STRIDE + a_q * 32;
        uint32_t h[8], l[8];
        cvt_split4(fA[0], h[0], h[1], l[0], l[1]);
        cvt_split4(fA[1], h[2], h[3], l[2], l[3]);
        cvt_split4(fA[2], h[4], h[5], l[4], l[5]);
        cvt_split4(fA[3], h[6], h[7], l[6], l[7]);
        *(uint4*)(ah)      = *(uint4*)&h[0];
        *(uint4*)(ah + 16) = *(uint4*)&h[4];
        *(uint4*)(al)      = *(uint4*)&l[0];
        *(uint4*)(al + 16) = *(uint4*)&l[4];
        *(uint4*)(smem + OFF_BHI(0) + b_row * SA_STRIDE + b_o * 2) = bhv;
        *(uint4*)(smem + OFF_BLO(0) + b_row * SA_STRIDE + b_o * 2) = blv;
    }
    __syncthreads();

    for (int kc = 0; kc < NCHUNK; kc++) {
        const int b = kc & 1;
        const bool has_next = (kc + 1 < NCHUNK);

        if (has_next) {
            const float* ga = Abase + (kc + 1) * 64;
            #pragma unroll
            for (int i = 0; i < 4; i++) fA[i] = ((const float4*)ga)[i];
            bhv = *(const uint4*)(Whi + (kc + 1) * 64);
            blv = *(const uint4*)(Wlo + (kc + 1) * 64);
        }

        const uint32_t ahi_b = sb + OFF_AHI(b) + a_lds;
        const uint32_t alo_b = sb + OFF_ALO(b) + a_lds;
        const uint32_t bhi_b = sb + OFF_BHI(b) + b_lds;
        const uint32_t blo_b = sb + OFF_BLO(b) + b_lds;

        #pragma unroll
        for (int ks = 0; ks < 4; ks++) {
            const uint32_t kb = ks * 32;
            uint32_t ah[2][4], al[2][4], bh[4], bl[4];
            #pragma unroll
            for (int mi = 0; mi < 2; mi++) {
                LDSM_X4(ah[mi][0], ah[mi][1], ah[mi][2], ah[mi][3],
                        ahi_b + mi * 16 * SA_STRIDE + kb);
                LDSM_X4(al[mi][0], al[mi][1], al[mi][2], al[mi][3],
                        alo_b + mi * 16 * SA_STRIDE + kb);
            }
            LDSM_X4(bh[0], bh[1], bh[2], bh[3], bhi_b + kb);
            LDSM_X4(bl[0], bl[1], bl[2], bl[3], blo_b + kb);

            #pragma unroll
            for (int mi = 0; mi < 2; mi++) {
                MMA16816(acc[mi][0], ah[mi][0], ah[mi][1], ah[mi][2], ah[mi][3], bh[0], bh[1]);
                MMA16816(acc[mi][1], ah[mi][0], ah[mi][1], ah[mi][2], ah[mi][3], bh[2], bh[3]);
                MMA16816(acc[mi][0], ah[mi][0], ah[mi][1], ah[mi][2], ah[mi][3], bl[0], bl[1]);
                MMA16816(acc[mi][1], ah[mi][0], ah[mi][1], ah[mi][2], ah[mi][3], bl[2], bl[3]);
                MMA16816(acc[mi][0], al[mi][0], al[mi][1], al[mi][2], al[mi][3], bh[0], bh[1]);
                MMA16816(acc[mi][1], al[mi][0], al[mi][1], al[mi][2], al[mi][3], bh[2], bh[3]);
            }
        }

        if (has_next) {
            const int nb = b ^ 1;
            char* ah = smem + OFF_AHI(nb) + a_row * SA_STRIDE + a_q * 32;
            char* al = smem + OFF_ALO(nb) + a_row * SA_STRIDE + a_q * 32;
            uint32_t h[8], l[8];
            cvt_split4(fA[0], h[0], h[1], l[0], l[1]);
            cvt_split4(fA[1], h[2], h[3], l[2], l[3]);
            cvt_split4(fA[2], h[4], h[5], l[4], l[5]);
            cvt_split4(fA[3], h[6], h[7], l[6], l[7]);
            *(uint4*)(ah)      = *(uint4*)&h[0];
            *(uint4*)(ah + 16) = *(uint4*)&h[4];
            *(uint4*)(al)      = *(uint4*)&l[0];
            *(uint4*)(al + 16) = *(uint4*)&l[4];
            *(uint4*)(smem + OFF_BHI(nb) + b_row * SA_STRIDE + b_o * 2) = bhv;
            *(uint4*)(smem + OFF_BLO(nb) + b_row * SA_STRIDE + b_o * 2) = blv;
            __syncthreads();
        }
    }

    // ---- epilogue: C -> smem; fused logits-write + parallel top-2 ----
    float* Cs   = (float*)smem;
    int*   cnts = (int*)(smem + CNT_OFF);   // [0:64) slot0, [64:128) slot1
    #pragma unroll
    for (int mi = 0; mi < 2; mi++) {
        #pragma unroll
        for (int ni = 0; ni < 2; ni++) {
            int r0 = wm * 32 + mi * 16 + (lane >> 2);
            int c  = wn * 16 + ni * 8 + (lane & 3) * 2;
            *(float2*)(Cs + r0 * CS + c)       = make_float2(acc[mi][ni][0], acc[mi][ni][1]);
            *(float2*)(Cs + (r0 + 8) * CS + c) = make_float2(acc[mi][ni][2], acc[mi][ni][3]);
        }
    }
    if (tid < 128) cnts[tid] = 0;
    __syncthreads();

    {
        // each thread: row r = tid>>2, 16-col quarter q = tid&3.
        const int r = tid >> 2;
        const int q = tid & 3;
        const int cb = q * 16;
        float* lrow = logits + (size_t)(block_m + r) * N_EXP + cb;
        const float* src = Cs + r * CS + cb;

        float m1 = -3.4e38f, m2 = -3.4e38f;
        int i1 = 0, i2 = 0;
        #pragma unroll
        for (int i = 0; i < 4; i++) {
            float2 u = *(const float2*)(src + i * 4);
            float2 v = *(const float2*)(src + i * 4 + 2);
            *(float4*)(lrow + i * 4) = make_float4(u.x, u.y, v.x, v.y);
            float vals[4] = {u.x, u.y, v.x, v.y};
            #pragma unroll
            for (int j = 0; j < 4; j++) {
                float val = vals[j];
                int e = cb + i * 4 + j;
                if (val > m1)      { m2 = m1; i2 = i1; m1 = val; i1 = e; }
                else if (val > m2) { m2 = val; i2 = e; }
            }
        }

        // butterfly merge across the 4 quarter-threads (lane bits 0,1)
        #pragma unroll
        for (int msk = 1; msk <= 2; msk <<= 1) {
            float om1 = __shfl_xor_sync(0xffffffffu, m1, msk);
            int   oi1 = __shfl_xor_sync(0xffffffffu, i1, msk);
            float om2 = __shfl_xor_sync(0xffffffffu, m2, msk);
            int   oi2 = __shfl_xor_sync(0xffffffffu, i2, msk);
            if (vgt(om1, oi1, m1, i1)) {
                if (vgt(m1, i1, om2, oi2)) { m2 = m1; i2 = i1; }
                else                       { m2 = om2; i2 = oi2; }
                m1 = om1; i1 = oi1;
            } else {
                if (vgt(om1, oi1, m2, i2)) { m2 = om1; i2 = oi1; }
            }
        }

        if (q == 0) {
            const int t = block_m + r;
            float w1 = 1.0f / (1.0f + __expf(m2 - m1));
            wflat[t * 2 + 0] = w1;
            wflat[t * 2 + 1] = 1.0f - w1;
            g_idx[t]            = i1;
            g_idx[T_TOKENS + t] = i2;
            atomicAdd(&cnts[i1], 1);
            atomicAdd(&cnts[64 + i2], 1);
        }
    }
    __syncthreads();
    if (tid < 64) {    // transposed [expert][segment]; CTA owns segs bm, 128+bm
        g_cnt[tid * 256 + bm]       = cnts[tid];
        g_cnt[tid * 256 + 128 + bm] = cnts[64 + tid];
    }
}

// ---------------------------------------------------------------------------
// Scan: one block per expert; coalesced load of g_cnt[e][0..255], 256-wide
// exclusive prefix, coalesced store to g_base[e][*]; zeros tail [total, CAP).
// ---------------------------------------------------------------------------
__global__ __launch_bounds__(256)
void scan_kernel(float* __restrict__ out_idx, float* __restrict__ out_w) {
    const int e = blockIdx.x;
    const int tid = threadIdx.x;
    const int lane = tid & 31, w = tid >> 5;

    int c = g_cnt[e * 256 + tid];
    int incl = c;
    #pragma unroll
    for (int off = 1; off < 32; off <<= 1) {
        int n = __shfl_up_sync(0xffffffffu, incl, off);
        if (lane >= off) incl += n;
    }
    __shared__ int wtot[8];
    if (lane == 31) wtot[w] = incl;
    __syncthreads();
    int woff = 0, total = 0;
    #pragma unroll
    for (int ww = 0; ww < 8; ww++) {
        int s = wtot[ww];
        if (ww < w) woff += s;
        total += s;
    }
    g_base[e * 256 + tid] = woff + incl - c;

    for (int i = total + tid; i < CAP; i += 256) {
        out_idx[e * CAP + i] = 0.0f;
        out_w[e * CAP + i]   = 0.0f;
    }
}

// ---------------------------------------------------------------------------
// Assign: grid (64 experts, 32), 8 warps/block; each warp handles one
// 128-entry segment: one int4 per lane, warp rank scan, scatter.
// ---------------------------------------------------------------------------
__global__ __launch_bounds__(256)
void assign_kernel(const float* __restrict__ wflat,
                   float* __restrict__ out_idx,
                   float* __restrict__ out_w) {
    const int e    = blockIdx.x;
    const int tid  = threadIdx.x;
    const int lane = tid & 31;
    const int s    = blockIdx.y * 8 + (tid >> 5);   // segment 0..255

    const int base = g_base[e * 256 + s];
    int4 v = ((const int4*)g_idx)[s * 32 + lane];

    int m0 = (v.x == e), m1 = (v.y == e), m2 = (v.z == e), m3 = (v.w == e);
    int cnt = m0 + m1 + m2 + m3;
    int inc = cnt;
    #pragma unroll
    for (int off = 1; off < 32; off <<= 1) {
        int n = __shfl_up_sync(0xffffffffu, inc, off);
        if (lane >= off) inc += n;
    }
    int pos = base + inc - cnt;

    if (cnt) {
        const int a0 = s * 128 + lane * 4;
        int comp[4] = {v.x, v.y, v.z, v.w};
        #pragma unroll
        for (int q = 0; q < 4; q++) {
            if (comp[q] == e) {
                if (pos < CAP) {
                    int a = a0 + q;
                    int token = a & (T_TOKENS - 1);
                    int slot  = a >> 14;
                    out_idx[e * CAP + pos] = (float)token;
                    out_w[e * CAP + pos]   = wflat[token * 2 + slot];
                }
                pos++;
            }
        }
    }
}

// ---------------------------------------------------------------------------
// Output layout (float32): [idx E*CAP | w E*CAP | wflat T*2 | logits T*E]
// ---------------------------------------------------------------------------
extern "C" void kernel_launch(void* const* d_in, const int* in_sizes, int n_in,
                              void* d_out, int out_size) {
    const float* hs;
    const float* wr;
    if (in_sizes[0] == N_EXP * H_DIM) {
        wr = (const float*)d_in[0];
        hs = (const float*)d_in[1];
    } else {
        hs = (const float*)d_in[0];
        wr = (const float*)d_in[1];
    }

    float* out     = (float*)d_out;
    float* out_idx = out;
    float* out_w   = out + N_EXP * CAP;
    float* wflat   = out + 2 * N_EXP * CAP;
    float* logits  = out + 2 * N_EXP * CAP + 2 * T_TOKENS;

    wconv_kernel<<<256, 256>>>(wr);
    cudaFuncSetAttribute(gemm_topk_kernel, cudaFuncAttributeMaxDynamicSharedMemorySize,
                         SMEM_BYTES);
    gemm_topk_kernel<<<T_TOKENS / 128, 512, SMEM_BYTES>>>(hs, logits, wflat);
    scan_kernel<<<N_EXP, 256>>>(out_idx, out_w);
    assign_kernel<<<dim3(N_EXP, 32), 256>>>(wflat, out_idx, out_w);
}

// round 16
// speedup vs baseline: 1.3932x; 1.0015x over previous
#include <cuda_runtime.h>
#include <cuda_bf16.h>
#include <cstdint>

#define T_TOKENS 16384
#define H_DIM    4096
#define N_EXP    64
#define CAP      320

__device__ __align__(16) int g_idx[2 * T_TOKENS];
__device__ __align__(16) int g_cnt[N_EXP * 256];    // [expert][segment]
__device__ __align__(16) int g_base[256 * N_EXP];   // [segment][expert] excl prefix
__device__ __align__(16) __nv_bfloat16 g_whi[N_EXP * H_DIM];
__device__ __align__(16) __nv_bfloat16 g_wlo[N_EXP * H_DIM];

// ---------------------------------------------------------------------------
// helpers
// ---------------------------------------------------------------------------
__device__ __forceinline__ uint32_t smem_to_u32(const void* p) {
    uint32_t a;
    asm("{ .reg .u64 t; cvta.to.shared.u64 t, %1; cvt.u32.u64 %0, t; }" : "=r"(a) : "l"(p));
    return a;
}

#define LDSM_X4(r0, r1, r2, r3, addr)                                          \
    asm volatile("ldmatrix.sync.aligned.m8n8.x4.shared.b16 {%0,%1,%2,%3}, [%4];" \
                 : "=r"(r0), "=r"(r1), "=r"(r2), "=r"(r3) : "r"(addr))

#define MMA16816(d, a0, a1, a2, a3, b0, b1)                                        \
    asm volatile(                                                                  \
        "mma.sync.aligned.m16n8k16.row.col.f32.bf16.bf16.f32 "                     \
        "{%0,%1,%2,%3}, {%4,%5,%6,%7}, {%8,%9}, {%0,%1,%2,%3};"                    \
        : "+f"((d)[0]), "+f"((d)[1]), "+f"((d)[2]), "+f"((d)[3])                   \
        : "r"(a0), "r"(a1), "r"(a2), "r"(a3), "r"(b0), "r"(b1))

__device__ __forceinline__ void cvt_split4(float4 f, uint32_t& h0, uint32_t& h1,
                                           uint32_t& l0, uint32_t& l1) {
    __nv_bfloat162 a = __floats2bfloat162_rn(f.x, f.y);
    __nv_bfloat162 b = __floats2bfloat162_rn(f.z, f.w);
    float r0 = f.x - __bfloat162float(a.x);
    float r1 = f.y - __bfloat162float(a.y);
    float r2 = f.z - __bfloat162float(b.x);
    float r3 = f.w - __bfloat162float(b.y);
    __nv_bfloat162 c = __floats2bfloat162_rn(r0, r1);
    __nv_bfloat162 d = __floats2bfloat162_rn(r2, r3);
    h0 = *(uint32_t*)&a; h1 = *(uint32_t*)&b;
    l0 = *(uint32_t*)&c; l1 = *(uint32_t*)&d;
}

// (value, index) "strictly better" with jax top_k tie-break (lower index wins)
__device__ __forceinline__ bool vgt(float v1, int i1, float v2, int i2) {
    return (v1 > v2) || (v1 == v2 && i1 < i2);
}

// ---------------------------------------------------------------------------
// smem: per buffer (BK=64): Ahi[128x64 bf16, stride 144B]=18432, Alo=18432,
// Bhi[64x64]=9216, Blo=9216 -> 55296; x2 = 110592 bytes.
// Epilogue: C (128x66 fp32 = 33792B) + counters (512B at 34048) reuse buf0.
// ---------------------------------------------------------------------------
#define SA_STRIDE 144
#define BUF_BYTES 55296
#define OFF_AHI(b) ((b) * BUF_BYTES + 0)
#define OFF_ALO(b) ((b) * BUF_BYTES + 18432)
#define OFF_BHI(b) ((b) * BUF_BYTES + 36864)
#define OFF_BLO(b) ((b) * BUF_BYTES + 46080)
#define SMEM_BYTES (2 * BUF_BYTES)
#define CS 66
#define CNT_OFF 34048

#define NCHUNK 64

// ---------------------------------------------------------------------------
// W pre-convert: fp32 -> bf16 hi + lo.  256 blocks x 256 thr, 4 floats/thread.
// ---------------------------------------------------------------------------
__global__ __launch_bounds__(256)
void wconv_kernel(const float* __restrict__ W) {
    const int i = (blockIdx.x * 256 + threadIdx.x) * 4;
    float4 f = *(const float4*)(W + i);
    uint32_t h0, h1, l0, l1;
    cvt_split4(f, h0, h1, l0, l1);
    *(uint2*)(g_whi + i) = make_uint2(h0, h1);
    *(uint2*)(g_wlo + i) = make_uint2(l0, l1);
}

// ---------------------------------------------------------------------------
// Fused GEMM (bf16 3-product split) + top-2 + per-segment hist epilogue.
// CTA: 128 tokens x 64 experts, K=4096. 512 threads, 16 warps: 4 M x 4 N.
// ---------------------------------------------------------------------------
__global__ __launch_bounds__(512, 1)
void gemm_topk_kernel(const float* __restrict__ A,
                      float* __restrict__ logits,
                      float* __restrict__ wflat) {
    extern __shared__ char smem[];
    const uint32_t sb = smem_to_u32(smem);
    const int tid  = threadIdx.x;
    const int wid  = tid >> 5;
    const int lane = tid & 31;
    const int wm   = wid & 3;     // rows [wm*32, +32)
    const int wn   = wid >> 2;    // cols [wn*16, +16)
    const int bm   = blockIdx.x;
    const int block_m = bm * 128;

    // global load coords
    const int a_row = tid >> 2;        // 0..127
    const int a_q   = tid & 3;         // 16-float quarter of 64-wide chunk
    const int b_row = tid >> 3;        // 0..63
    const int b_o   = (tid & 7) * 8;   // 8 bf16

    const float* Abase = A + (size_t)(block_m + a_row) * H_DIM + a_q * 16;
    const __nv_bfloat16* Whi = g_whi + (size_t)b_row * H_DIM + b_o;
    const __nv_bfloat16* Wlo = g_wlo + (size_t)b_row * H_DIM + b_o;

    const uint32_t a_lds = (uint32_t)((wm * 32 + (lane & 15)) * SA_STRIDE + (lane >> 4) * 16);
    const uint32_t b_lds = (uint32_t)((wn * 16 + (lane & 7) + ((lane >> 4) & 1) * 8) * SA_STRIDE +
                                      ((lane >> 3) & 1) * 16);

    float acc[2][2][4];
    #pragma unroll
    for (int i = 0; i < 2; i++)
        #pragma unroll
        for (int j = 0; j < 2; j++)
            #pragma unroll
            for (int q = 0; q < 4; q++) acc[i][j][q] = 0.0f;

    float4 fA[4];
    uint4 bhv, blv;

    // ---- prologue: chunk 0 -> buffer 0 ----
    #pragma unroll
    for (int i = 0; i < 4; i++) fA[i] = ((const float4*)Abase)[i];
    bhv = *(const uint4*)Whi;
    blv = *(const uint4*)Wlo;
    {
        char* ah = smem + OFF_AHI(0) + a_row * SA_STRIDE + a_q * 32;
        char* al = smem + OFF_ALO(0) + a_row * SA_STRIDE + a_q * 32;
        uint32_t h[8], l[8];
        cvt_split4(fA[0], h[0], h[1], l[0], l[1]);
        cvt_split4(fA[1], h[2], h[3], l[2], l[3]);
        cvt_split4(fA[2], h[4], h[5], l[4], l[5]);
        cvt_split4(fA[3], h[6], h[7], l[6], l[7]);
        *(uint4*)(ah)      = *(uint4*)&h[0];
        *(uint4*)(ah + 16) = *(uint4*)&h[4];
        *(uint4*)(al)      = *(uint4*)&l[0];
        *(uint4*)(al + 16) = *(uint4*)&l[4];
        *(uint4*)(smem + OFF_BHI(0) + b_row * SA_STRIDE + b_o * 2) = bhv;
        *(uint4*)(smem + OFF_BLO(0) + b_row * SA_STRIDE + b_o * 2) = blv;
    }
    __syncthreads();

    for (int kc = 0; kc < NCHUNK; kc++) {
        const int b = kc & 1;
        const bool has_next = (kc + 1 < NCHUNK);

        if (has_next) {
            const float* ga = Abase + (kc + 1) * 64;
            #pragma unroll
            for (int i = 0; i < 4; i++) fA[i] = ((const float4*)ga)[i];
            bhv = *(const uint4*)(Whi + (kc + 1) * 64);
            blv = *(const uint4*)(Wlo + (kc + 1) * 64);
        }

        const uint32_t ahi_b = sb + OFF_AHI(b) + a_lds;
        const uint32_t alo_b = sb + OFF_ALO(b) + a_lds;
        const uint32_t bhi_b = sb + OFF_BHI(b) + b_lds;
        const uint32_t blo_b = sb + OFF_BLO(b) + b_lds;

        #pragma unroll
        for (int ks = 0; ks < 4; ks++) {
            const uint32_t kb = ks * 32;
            uint32_t ah[2][4], al[2][4], bh[4], bl[4];
            #pragma unroll
            for (int mi = 0; mi < 2; mi++) {
                LDSM_X4(ah[mi][0], ah[mi][1], ah[mi][2], ah[mi][3],
                        ahi_b + mi * 16 * SA_STRIDE + kb);
                LDSM_X4(al[mi][0], al[mi][1], al[mi][2], al[mi][3],
                        alo_b + mi * 16 * SA_STRIDE + kb);
            }
            LDSM_X4(bh[0], bh[1], bh[2], bh[3], bhi_b + kb);
            LDSM_X4(bl[0], bl[1], bl[2], bl[3], blo_b + kb);

            #pragma unroll
            for (int mi = 0; mi < 2; mi++) {
                MMA16816(acc[mi][0], ah[mi][0], ah[mi][1], ah[mi][2], ah[mi][3], bh[0], bh[1]);
                MMA16816(acc[mi][1], ah[mi][0], ah[mi][1], ah[mi][2], ah[mi][3], bh[2], bh[3]);
                MMA16816(acc[mi][0], ah[mi][0], ah[mi][1], ah[mi][2], ah[mi][3], bl[0], bl[1]);
                MMA16816(acc[mi][1], ah[mi][0], ah[mi][1], ah[mi][2], ah[mi][3], bl[2], bl[3]);
                MMA16816(acc[mi][0], al[mi][0], al[mi][1], al[mi][2], al[mi][3], bh[0], bh[1]);
                MMA16816(acc[mi][1], al[mi][0], al[mi][1], al[mi][2], al[mi][3], bh[2], bh[3]);
            }
        }

        if (has_next) {
            const int nb = b ^ 1;
            char* ah = smem + OFF_AHI(nb) + a_row * SA_STRIDE + a_q * 32;
            char* al = smem + OFF_ALO(nb) + a_row * SA_STRIDE + a_q * 32;
            uint32_t h[8], l[8];
            cvt_split4(fA[0], h[0], h[1], l[0], l[1]);
            cvt_split4(fA[1], h[2], h[3], l[2], l[3]);
            cvt_split4(fA[2], h[4], h[5], l[4], l[5]);
            cvt_split4(fA[3], h[6], h[7], l[6], l[7]);
            *(uint4*)(ah)      = *(uint4*)&h[0];
            *(uint4*)(ah + 16) = *(uint4*)&h[4];
            *(uint4*)(al)      = *(uint4*)&l[0];
            *(uint4*)(al + 16) = *(uint4*)&l[4];
            *(uint4*)(smem + OFF_BHI(nb) + b_row * SA_STRIDE + b_o * 2) = bhv;
            *(uint4*)(smem + OFF_BLO(nb) + b_row * SA_STRIDE + b_o * 2) = blv;
            __syncthreads();
        }
    }

    // ---- epilogue: C -> smem; fused logits-write + parallel top-2 ----
    float* Cs   = (float*)smem;
    int*   cnts = (int*)(smem + CNT_OFF);   // [0:64) slot0, [64:128) slot1
    #pragma unroll
    for (int mi = 0; mi < 2; mi++) {
        #pragma unroll
        for (int ni = 0; ni < 2; ni++) {
            int r0 = wm * 32 + mi * 16 + (lane >> 2);
            int c  = wn * 16 + ni * 8 + (lane & 3) * 2;
            *(float2*)(Cs + r0 * CS + c)       = make_float2(acc[mi][ni][0], acc[mi][ni][1]);
            *(float2*)(Cs + (r0 + 8) * CS + c) = make_float2(acc[mi][ni][2], acc[mi][ni][3]);
        }
    }
    if (tid < 128) cnts[tid] = 0;
    __syncthreads();

    {
        // each thread: row r = tid>>2, 16-col quarter q = tid&3.
        const int r = tid >> 2;
        const int q = tid & 3;
        const int cb = q * 16;
        float* lrow = logits + (size_t)(block_m + r) * N_EXP + cb;
        const float* src = Cs + r * CS + cb;

        float m1 = -3.4e38f, m2 = -3.4e38f;
        int i1 = 0, i2 = 0;
        #pragma unroll
        for (int i = 0; i < 4; i++) {
            float2 u = *(const float2*)(src + i * 4);
            float2 v = *(const float2*)(src + i * 4 + 2);
            *(float4*)(lrow + i * 4) = make_float4(u.x, u.y, v.x, v.y);
            float vals[4] = {u.x, u.y, v.x, v.y};
            #pragma unroll
            for (int j = 0; j < 4; j++) {
                float val = vals[j];
                int e = cb + i * 4 + j;
                if (val > m1)      { m2 = m1; i2 = i1; m1 = val; i1 = e; }
                else if (val > m2) { m2 = val; i2 = e; }
            }
        }

        // butterfly merge across the 4 quarter-threads (lane bits 0,1)
        #pragma unroll
        for (int msk = 1; msk <= 2; msk <<= 1) {
            float om1 = __shfl_xor_sync(0xffffffffu, m1, msk);
            int   oi1 = __shfl_xor_sync(0xffffffffu, i1, msk);
            float om2 = __shfl_xor_sync(0xffffffffu, m2, msk);
            int   oi2 = __shfl_xor_sync(0xffffffffu, i2, msk);
            if (vgt(om1, oi1, m1, i1)) {
                if (vgt(m1, i1, om2, oi2)) { m2 = m1; i2 = i1; }
                else                       { m2 = om2; i2 = oi2; }
                m1 = om1; i1 = oi1;
            } else {
                if (vgt(om1, oi1, m2, i2)) { m2 = om1; i2 = oi1; }
            }
        }

        if (q == 0) {
            const int t = block_m + r;
            float w1 = 1.0f / (1.0f + __expf(m2 - m1));
            wflat[t * 2 + 0] = w1;
            wflat[t * 2 + 1] = 1.0f - w1;
            g_idx[t]            = i1;
            g_idx[T_TOKENS + t] = i2;
            atomicAdd(&cnts[i1], 1);
            atomicAdd(&cnts[64 + i2], 1);
        }
    }
    __syncthreads();
    if (tid < 64) {    // transposed [expert][segment]; CTA owns segs bm, 128+bm
        g_cnt[tid * 256 + bm]       = cnts[tid];
        g_cnt[tid * 256 + 128 + bm] = cnts[64 + tid];
    }
}

// ---------------------------------------------------------------------------
// Scan: one block per expert; coalesced load of g_cnt[e][0..255], 256-wide
// exclusive prefix, store to g_base[segment][e]; zeros tail [total, CAP).
// ---------------------------------------------------------------------------
__global__ __launch_bounds__(256)
void scan_kernel(float* __restrict__ out_idx, float* __restrict__ out_w) {
    const int e = blockIdx.x;
    const int tid = threadIdx.x;
    const int lane = tid & 31, w = tid >> 5;

    int c = g_cnt[e * 256 + tid];
    int incl = c;
    #pragma unroll
    for (int off = 1; off < 32; off <<= 1) {
        int n = __shfl_up_sync(0xffffffffu, incl, off);
        if (lane >= off) incl += n;
    }
    __shared__ int wtot[8];
    if (lane == 31) wtot[w] = incl;
    __syncthreads();
    int woff = 0, total = 0;
    #pragma unroll
    for (int ww = 0; ww < 8; ww++) {
        int s = wtot[ww];
        if (ww < w) woff += s;
        total += s;
    }
    g_base[tid * N_EXP + e] = woff + incl - c;   // [segment][expert]

    for (int i = total + tid; i < CAP; i += 256) {
        out_idx[e * CAP + i] = 0.0f;
        out_w[e * CAP + i]   = 0.0f;
    }
}

// ---------------------------------------------------------------------------
// Assign (token-side): grid 32 x 256 threads; each warp owns one 128-entry
// segment. 4 phases of 32 entries in token order; __match_any_sync groups
// lanes by expert, per-warp smem counters carry ranks across phases.
// g_idx is read exactly once (vs once-per-expert before).
// ---------------------------------------------------------------------------
__global__ __launch_bounds__(256)
void assign_kernel(const float* __restrict__ wflat,
                   float* __restrict__ out_idx,
                   float* __restrict__ out_w) {
    __shared__ int cnt_s[8][N_EXP];
    const int tid  = threadIdx.x;
    const int lane = tid & 31;
    const int w    = tid >> 5;
    const int s    = blockIdx.x * 8 + w;    // segment 0..255
    volatile int* cnt = cnt_s[w];

    cnt[lane]      = 0;
    cnt[lane + 32] = 0;

    // per-segment bases: lane l holds base[s][l] and base[s][l+32]
    const int base0 = g_base[s * N_EXP + lane];
    const int base1 = g_base[s * N_EXP + 32 + lane];

    // entries in token order: phase q handles entry q*32 + lane
    int ev[4];
    #pragma unroll
    for (int q = 0; q < 4; q++) ev[q] = g_idx[s * 128 + q * 32 + lane];

    __syncwarp();

    #pragma unroll
    for (int q = 0; q < 4; q++) {
        const int e = ev[q];
        unsigned mask = __match_any_sync(0xffffffffu, e);
        int prior = __popc(mask & ((1u << lane) - 1u));
        int c = cnt[e];                       // same value across the match group
        int b0 = __shfl_sync(0xffffffffu, base0, e & 31);
        int b1 = __shfl_sync(0xffffffffu, base1, e & 31);
        int pos = ((e < 32) ? b0 : b1) + c + prior;
        __syncwarp();
        if (prior == 0) cnt[e] = c + __popc(mask);   // group leader advances
        __syncwarp();

        if (pos < CAP) {
            const int a = s * 128 + q * 32 + lane;
            const int token = a & (T_TOKENS - 1);
            const int slot  = a >> 14;
            out_idx[e * CAP + pos] = (float)token;
            out_w[e * CAP + pos]   = wflat[token * 2 + slot];
        }
    }
}

// ---------------------------------------------------------------------------
// Output layout (float32): [idx E*CAP | w E*CAP | wflat T*2 | logits T*E]
// ---------------------------------------------------------------------------
extern "C" void kernel_launch(void* const* d_in, const int* in_sizes, int n_in,
                              void* d_out, int out_size) {
    const float* hs;
    const float* wr;
    if (in_sizes[0] == N_EXP * H_DIM) {
        wr = (const float*)d_in[0];
        hs = (const float*)d_in[1];
    } else {
        hs = (const float*)d_in[0];
        wr = (const float*)d_in[1];
    }

    float* out     = (float*)d_out;
    float* out_idx = out;
    float* out_w   = out + N_EXP * CAP;
    float* wflat   = out + 2 * N_EXP * CAP;
    float* logits  = out + 2 * N_EXP * CAP + 2 * T_TOKENS;

    wconv_kernel<<<256, 256>>>(wr);
    cudaFuncSetAttribute(gemm_topk_kernel, cudaFuncAttributeMaxDynamicSharedMemorySize,
                         SMEM_BYTES);
    gemm_topk_kernel<<<T_TOKENS / 128, 512, SMEM_BYTES>>>(hs, logits, wflat);
    scan_kernel<<<N_EXP, 256>>>(out_idx, out_w);
    assign_kernel<<<32, 256>>>(wflat, out_idx, out_w);
}